// round 1
// baseline (speedup 1.0000x reference)
#include <cuda_runtime.h>
#include <cuda_bf16.h>
#include <math.h>

// Problem constants
#define BATCH 2
#define NSEQ 2048
#define TOK   4096           // BATCH*NSEQ
#define CDIM  1024
#define C3    3072
#define HID   4096
#define NHEAD 16
#define HDIM  64

// ---------------- scratch (device globals; no allocation allowed) ----------------
__device__ float g_xn  [TOK * CDIM];   // LN output (reused for ln1 and ln2)
__device__ float g_qkv [TOK * C3];     // qkv projection
__device__ float g_attn[TOK * CDIM];   // attention output (pre-proj)
__device__ float g_x1  [TOK * CDIM];   // x + attn_proj
__device__ float g_h   [TOK * HID];    // gelu(fc1)

// ---------------- LayerNorm: one block per row of 1024 ----------------
__global__ void ln_kernel(const float* __restrict__ x,
                          const float* __restrict__ g,
                          const float* __restrict__ b,
                          float* __restrict__ out) {
    int row = blockIdx.x;
    int tid = threadIdx.x;                    // 256 threads, 4 floats each
    const float4* xr = (const float4*)(x + (size_t)row * CDIM);
    float4 v = xr[tid];
    float s = v.x + v.y + v.z + v.w;
    float q = v.x*v.x + v.y*v.y + v.z*v.z + v.w*v.w;
    #pragma unroll
    for (int m = 16; m; m >>= 1) {
        s += __shfl_xor_sync(0xffffffffu, s, m);
        q += __shfl_xor_sync(0xffffffffu, q, m);
    }
    __shared__ float rs[8], rq[8];
    __shared__ float s_mu, s_rstd;
    int w = tid >> 5, ln = tid & 31;
    if (!ln) { rs[w] = s; rq[w] = q; }
    __syncthreads();
    if (tid == 0) {
        float ts = 0.f, tq = 0.f;
        #pragma unroll
        for (int i = 0; i < 8; i++) { ts += rs[i]; tq += rq[i]; }
        float mu = ts * (1.0f / CDIM);
        float var = tq * (1.0f / CDIM) - mu * mu;
        s_mu = mu;
        s_rstd = rsqrtf(var + 1e-5f);
    }
    __syncthreads();
    float mu = s_mu, r = s_rstd;
    float4 gv = ((const float4*)g)[tid];
    float4 bv = ((const float4*)b)[tid];
    float4 o;
    o.x = (v.x - mu) * r * gv.x + bv.x;
    o.y = (v.y - mu) * r * gv.y + bv.y;
    o.z = (v.z - mu) * r * gv.z + bv.z;
    o.w = (v.w - mu) * r * gv.w + bv.w;
    ((float4*)(out + (size_t)row * CDIM))[tid] = o;
}

// ---------------- SGEMM NT: out[M,N] = A[M,K] @ W[N,K]^T (+bias)(+act)(+res) ------
// 128x128 tile, BK=16, 256 threads, 8x8 per thread.
// ACT: 0 = none, 1 = exact GELU
template<int ACT>
__global__ __launch_bounds__(256, 2)
void gemm_nt(const float* __restrict__ A, const float* __restrict__ W,
             const float* __restrict__ bias, const float* __restrict__ res,
             float* __restrict__ out, int M, int N, int K) {
    __shared__ float As[16][128];
    __shared__ float Ws[16][128];
    int tid = threadIdx.x;
    int bn = blockIdx.x * 128, bm = blockIdx.y * 128;
    int tx = tid & 15, ty = tid >> 4;
    int lr = tid >> 2, lc = tid & 3;

    const float* Ap = A + (size_t)(bm + lr) * K + lc * 4;
    const float* Wp = W + (size_t)(bn + lr) * K + lc * 4;

    float acc[8][8];
    #pragma unroll
    for (int i = 0; i < 8; i++)
        #pragma unroll
        for (int j = 0; j < 8; j++) acc[i][j] = 0.f;

    for (int kt = 0; kt < K; kt += 16) {
        #pragma unroll
        for (int i = 0; i < 2; i++) {
            float4 a4 = *(const float4*)(Ap + (size_t)i * 64 * K + kt);
            As[lc*4+0][lr + i*64] = a4.x;
            As[lc*4+1][lr + i*64] = a4.y;
            As[lc*4+2][lr + i*64] = a4.z;
            As[lc*4+3][lr + i*64] = a4.w;
            float4 w4 = *(const float4*)(Wp + (size_t)i * 64 * K + kt);
            Ws[lc*4+0][lr + i*64] = w4.x;
            Ws[lc*4+1][lr + i*64] = w4.y;
            Ws[lc*4+2][lr + i*64] = w4.z;
            Ws[lc*4+3][lr + i*64] = w4.w;
        }
        __syncthreads();
        #pragma unroll
        for (int kk = 0; kk < 16; kk++) {
            float4 a0 = *(const float4*)&As[kk][ty*8];
            float4 a1 = *(const float4*)&As[kk][ty*8 + 4];
            float4 w0 = *(const float4*)&Ws[kk][tx*8];
            float4 w1 = *(const float4*)&Ws[kk][tx*8 + 4];
            float a[8] = {a0.x,a0.y,a0.z,a0.w,a1.x,a1.y,a1.z,a1.w};
            float w[8] = {w0.x,w0.y,w0.z,w0.w,w1.x,w1.y,w1.z,w1.w};
            #pragma unroll
            for (int i = 0; i < 8; i++)
                #pragma unroll
                for (int j = 0; j < 8; j++)
                    acc[i][j] += a[i] * w[j];
        }
        __syncthreads();
    }

    // epilogue
    float bv[8];
    #pragma unroll
    for (int j = 0; j < 8; j++) bv[j] = bias ? bias[bn + tx*8 + j] : 0.f;

    #pragma unroll
    for (int i = 0; i < 8; i++) {
        int row = bm + ty*8 + i;
        float v[8];
        #pragma unroll
        for (int j = 0; j < 8; j++) {
            float t = acc[i][j] + bv[j];
            if (ACT == 1)
                t = 0.5f * t * (1.0f + erff(t * 0.70710678118654752f));
            v[j] = t;
        }
        size_t obase = (size_t)row * N + bn + tx*8;
        if (res) {
            float4 r0 = *(const float4*)(res + obase);
            float4 r1 = *(const float4*)(res + obase + 4);
            v[0]+=r0.x; v[1]+=r0.y; v[2]+=r0.z; v[3]+=r0.w;
            v[4]+=r1.x; v[5]+=r1.y; v[6]+=r1.z; v[7]+=r1.w;
        }
        *(float4*)(out + obase)     = make_float4(v[0],v[1],v[2],v[3]);
        *(float4*)(out + obase + 4) = make_float4(v[4],v[5],v[6],v[7]);
    }
}

// ---------------- Flash attention (fp32) ----------------
// Block: (q-tile of 128 rows) x head x batch. Bk = 64. 256 threads.
// Thread computes 8 rows x 4 cols of S, owns 8 rows x 4 d-cols of O.
#define ATTN_SMEM_FLOATS (64*128 + 64*64 + 64*68 + 128*68)
#define ATTN_SMEM_BYTES  (ATTN_SMEM_FLOATS * 4)

__global__ __launch_bounds__(256)
void attn_kernel(const float* __restrict__ qkv, float* __restrict__ out) {
    extern __shared__ float sm[];
    float* Qt = sm;                       // [64][128] d-major (q pre-scaled)
    float* Kt = Qt + 64*128;              // [64][64]  d-major
    float* Vs = Kt + 64*64;               // [64][68]  n-major (pad 68)
    float* Ps = Vs + 64*68;               // [128][68] r-major (pad 68)

    int tid = threadIdx.x;
    int h = blockIdx.y;
    size_t tb = (size_t)blockIdx.z * NSEQ;
    int q0 = blockIdx.x * 128;

    // load Q tile (128 x 64), transpose into Qt[d][r], pre-scale by 1/sqrt(64)
    {
        int r = tid >> 1;
        int c0 = (tid & 1) * 32;
        const float* src = qkv + (tb + q0 + r) * C3 + h * HDIM + c0;
        #pragma unroll
        for (int k = 0; k < 8; k++) {
            float4 v = *(const float4*)(src + k*4);
            int d = c0 + k*4;
            Qt[(d+0)*128 + r] = v.x * 0.125f;
            Qt[(d+1)*128 + r] = v.y * 0.125f;
            Qt[(d+2)*128 + r] = v.z * 0.125f;
            Qt[(d+3)*128 + r] = v.w * 0.125f;
        }
    }

    int ty = tid >> 4, tx = tid & 15;
    float mi[8], li[8], acc[8][4];
    #pragma unroll
    for (int i = 0; i < 8; i++) {
        mi[i] = -1e30f; li[i] = 0.f;
        #pragma unroll
        for (int c = 0; c < 4; c++) acc[i][c] = 0.f;
    }

    for (int n0 = 0; n0 < NSEQ; n0 += 64) {
        // load K (transposed) and V tiles
        {
            int r = tid >> 2;
            int c0 = (tid & 3) * 16;
            const float* ksrc = qkv + (tb + n0 + r) * C3 + CDIM + h * HDIM + c0;
            const float* vsrc = ksrc + CDIM;
            #pragma unroll
            for (int k = 0; k < 4; k++) {
                float4 kv = *(const float4*)(ksrc + k*4);
                int d = c0 + k*4;
                Kt[(d+0)*64 + r] = kv.x;
                Kt[(d+1)*64 + r] = kv.y;
                Kt[(d+2)*64 + r] = kv.z;
                Kt[(d+3)*64 + r] = kv.w;
                float4 vv = *(const float4*)(vsrc + k*4);
                *(float4*)(Vs + r*68 + c0 + k*4) = vv;
            }
        }
        __syncthreads();

        // S = Q @ K^T  (8x4 per thread, inner over d)
        float s[8][4];
        #pragma unroll
        for (int i = 0; i < 8; i++)
            #pragma unroll
            for (int c = 0; c < 4; c++) s[i][c] = 0.f;

        #pragma unroll 8
        for (int d = 0; d < 64; d++) {
            float4 a0 = *(const float4*)(Qt + d*128 + ty*8);
            float4 a1 = *(const float4*)(Qt + d*128 + ty*8 + 4);
            float4 kv = *(const float4*)(Kt + d*64 + tx*4);
            float aa[8] = {a0.x,a0.y,a0.z,a0.w,a1.x,a1.y,a1.z,a1.w};
            float kk[4] = {kv.x,kv.y,kv.z,kv.w};
            #pragma unroll
            for (int i = 0; i < 8; i++)
                #pragma unroll
                for (int c = 0; c < 4; c++)
                    s[i][c] += aa[i] * kk[c];
        }

        // online softmax (row groups = 16 consecutive lanes)
        #pragma unroll
        for (int i = 0; i < 8; i++) {
            float mx = fmaxf(fmaxf(s[i][0], s[i][1]), fmaxf(s[i][2], s[i][3]));
            #pragma unroll
            for (int mk = 8; mk; mk >>= 1)
                mx = fmaxf(mx, __shfl_xor_sync(0xffffffffu, mx, mk));
            float mnew = fmaxf(mi[i], mx);
            float al = __expf(mi[i] - mnew);
            float p0 = __expf(s[i][0] - mnew);
            float p1 = __expf(s[i][1] - mnew);
            float p2 = __expf(s[i][2] - mnew);
            float p3 = __expf(s[i][3] - mnew);
            float ps = p0 + p1 + p2 + p3;
            #pragma unroll
            for (int mk = 8; mk; mk >>= 1)
                ps += __shfl_xor_sync(0xffffffffu, ps, mk);
            li[i] = li[i] * al + ps;
            mi[i] = mnew;
            acc[i][0] *= al; acc[i][1] *= al; acc[i][2] *= al; acc[i][3] *= al;
            *(float4*)(Ps + (ty*8 + i) * 68 + tx*4) = make_float4(p0, p1, p2, p3);
        }
        __syncthreads();

        // O += P @ V  (inner over j in chunks of 4)
        #pragma unroll 4
        for (int j4 = 0; j4 < 16; j4++) {
            float4 v0 = *(const float4*)(Vs + (j4*4+0)*68 + tx*4);
            float4 v1 = *(const float4*)(Vs + (j4*4+1)*68 + tx*4);
            float4 v2 = *(const float4*)(Vs + (j4*4+2)*68 + tx*4);
            float4 v3 = *(const float4*)(Vs + (j4*4+3)*68 + tx*4);
            #pragma unroll
            for (int i = 0; i < 8; i++) {
                float4 p = *(const float4*)(Ps + (ty*8 + i) * 68 + j4*4);
                acc[i][0] += p.x*v0.x + p.y*v1.x + p.z*v2.x + p.w*v3.x;
                acc[i][1] += p.x*v0.y + p.y*v1.y + p.z*v2.y + p.w*v3.y;
                acc[i][2] += p.x*v0.z + p.y*v1.z + p.z*v2.z + p.w*v3.z;
                acc[i][3] += p.x*v0.w + p.y*v1.w + p.z*v2.w + p.w*v3.w;
            }
        }
        __syncthreads();
    }

    // write O (normalize by l)
    #pragma unroll
    for (int i = 0; i < 8; i++) {
        float inv = 1.0f / li[i];
        float4 o = make_float4(acc[i][0]*inv, acc[i][1]*inv, acc[i][2]*inv, acc[i][3]*inv);
        *(float4*)(out + (tb + q0 + ty*8 + i) * CDIM + h * HDIM + tx*4) = o;
    }
}

// ---------------- launch ----------------
extern "C" void kernel_launch(void* const* d_in, const int* in_sizes, int n_in,
                              void* d_out, int out_size) {
    const float* x      = (const float*)d_in[0];
    const float* w_qkv  = (const float*)d_in[1];
    const float* w_proj = (const float*)d_in[2];
    const float* b_proj = (const float*)d_in[3];
    const float* ln1_g  = (const float*)d_in[4];
    const float* ln1_b  = (const float*)d_in[5];
    const float* ln2_g  = (const float*)d_in[6];
    const float* ln2_b  = (const float*)d_in[7];
    const float* w_fc1  = (const float*)d_in[8];
    const float* b_fc1  = (const float*)d_in[9];
    const float* w_fc2  = (const float*)d_in[10];
    const float* b_fc2  = (const float*)d_in[11];
    float* out = (float*)d_out;

    float *xn, *qkv, *attn, *x1, *hbuf;
    cudaGetSymbolAddress((void**)&xn,   g_xn);
    cudaGetSymbolAddress((void**)&qkv,  g_qkv);
    cudaGetSymbolAddress((void**)&attn, g_attn);
    cudaGetSymbolAddress((void**)&x1,   g_x1);
    cudaGetSymbolAddress((void**)&hbuf, g_h);

    cudaFuncSetAttribute(attn_kernel, cudaFuncAttributeMaxDynamicSharedMemorySize,
                         ATTN_SMEM_BYTES);

    // 1) ln1
    ln_kernel<<<TOK, 256>>>(x, ln1_g, ln1_b, xn);
    // 2) qkv = ln1(x) @ w_qkv^T
    gemm_nt<0><<<dim3(C3/128, TOK/128), 256>>>(xn, w_qkv, nullptr, nullptr, qkv,
                                               TOK, C3, CDIM);
    // 3) attention
    attn_kernel<<<dim3(NSEQ/128, NHEAD, BATCH), 256, ATTN_SMEM_BYTES>>>(qkv, attn);
    // 4) x1 = x + attn @ w_proj^T + b_proj
    gemm_nt<0><<<dim3(CDIM/128, TOK/128), 256>>>(attn, w_proj, b_proj, x, x1,
                                                 TOK, CDIM, CDIM);
    // 5) ln2
    ln_kernel<<<TOK, 256>>>(x1, ln2_g, ln2_b, xn);
    // 6) h = gelu(ln2 @ w_fc1^T + b_fc1)
    gemm_nt<1><<<dim3(HID/128, TOK/128), 256>>>(xn, w_fc1, b_fc1, nullptr, hbuf,
                                                TOK, HID, CDIM);
    // 7) out = x1 + h @ w_fc2^T + b_fc2
    gemm_nt<0><<<dim3(CDIM/128, TOK/128), 256>>>(hbuf, w_fc2, b_fc2, x1, out,
                                                 TOK, CDIM, HID);
}

// round 13
// speedup vs baseline: 1.8882x; 1.8882x over previous
#include <cuda_runtime.h>
#include <cuda_bf16.h>
#include <math.h>
#include <stdint.h>

// Problem constants
#define BATCH 2
#define NSEQ 2048
#define TOK   4096           // BATCH*NSEQ
#define CDIM  1024
#define C3    3072
#define HID   4096
#define NHEAD 16
#define HDIM  64

// ---------------- scratch (device globals; no allocation allowed) ----------------
__device__ float g_xn  [TOK * CDIM];
__device__ float g_qkv [TOK * C3];
__device__ float g_attn[TOK * CDIM];
__device__ float g_x1  [TOK * CDIM];
__device__ float g_h   [TOK * HID];

// ================= helpers =================
__device__ __forceinline__ uint32_t smem_u32(const void* p) {
    uint32_t a;
    asm("{ .reg .u64 t; cvta.to.shared.u64 t, %1; cvt.u32.u64 %0, t; }"
        : "=r"(a) : "l"(p));
    return a;
}
__device__ __forceinline__ void ldsm4(uint32_t* r, uint32_t addr) {
    asm volatile("ldmatrix.sync.aligned.m8n8.x4.shared.b16 {%0,%1,%2,%3}, [%4];"
                 : "=r"(r[0]), "=r"(r[1]), "=r"(r[2]), "=r"(r[3]) : "r"(addr));
}
__device__ __forceinline__ void mma16816(float* c, const uint32_t* a,
                                         uint32_t b0, uint32_t b1) {
    asm volatile(
        "mma.sync.aligned.m16n8k16.row.col.f32.bf16.bf16.f32 "
        "{%0,%1,%2,%3}, {%4,%5,%6,%7}, {%8,%9}, {%0,%1,%2,%3};"
        : "+f"(c[0]), "+f"(c[1]), "+f"(c[2]), "+f"(c[3])
        : "r"(a[0]), "r"(a[1]), "r"(a[2]), "r"(a[3]), "r"(b0), "r"(b1));
}

// ---------------- LayerNorm ----------------
__global__ void ln_kernel(const float* __restrict__ x,
                          const float* __restrict__ g,
                          const float* __restrict__ b,
                          float* __restrict__ out) {
    int row = blockIdx.x;
    int tid = threadIdx.x;
    const float4* xr = (const float4*)(x + (size_t)row * CDIM);
    float4 v = xr[tid];
    float s = v.x + v.y + v.z + v.w;
    float q = v.x*v.x + v.y*v.y + v.z*v.z + v.w*v.w;
    #pragma unroll
    for (int m = 16; m; m >>= 1) {
        s += __shfl_xor_sync(0xffffffffu, s, m);
        q += __shfl_xor_sync(0xffffffffu, q, m);
    }
    __shared__ float rs[8], rq[8];
    __shared__ float s_mu, s_rstd;
    int w = tid >> 5, ln = tid & 31;
    if (!ln) { rs[w] = s; rq[w] = q; }
    __syncthreads();
    if (tid == 0) {
        float ts = 0.f, tq = 0.f;
        #pragma unroll
        for (int i = 0; i < 8; i++) { ts += rs[i]; tq += rq[i]; }
        float mu = ts * (1.0f / CDIM);
        float var = tq * (1.0f / CDIM) - mu * mu;
        s_mu = mu;
        s_rstd = rsqrtf(var + 1e-5f);
    }
    __syncthreads();
    float mu = s_mu, r = s_rstd;
    float4 gv = ((const float4*)g)[tid];
    float4 bv = ((const float4*)b)[tid];
    float4 o;
    o.x = (v.x - mu) * r * gv.x + bv.x;
    o.y = (v.y - mu) * r * gv.y + bv.y;
    o.z = (v.z - mu) * r * gv.z + bv.z;
    o.w = (v.w - mu) * r * gv.w + bv.w;
    ((float4*)(out + (size_t)row * CDIM))[tid] = o;
}

// ====== split-bf16 mma.sync GEMM NT: out[M,N] = A[M,K] @ W[N,K]^T ======
// CTA: 128x128 tile, BK=32, 256 threads = 8 warps (2m x 4n), warp tile 64x32.
// Split: A=Ah+Al, B=Bh+Bl; acc += AhBh + AhBl + AlBh  (fp32 accumulate).
// Smem per stage: Ah,Al,Wh,Wl each 128 rows x 40 bf16 (80B stride) = 10240B.
#define KPAD 40
#define MAT_BYTES (128 * KPAD * 2)          // 10240
#define STAGE_BYTES (4 * MAT_BYTES)         // 40960
#define GEMM_SMEM (2 * STAGE_BYTES)         // 81920

template<int ACT>
__global__ __launch_bounds__(256, 2)
void gemm_mma(const float* __restrict__ A, const float* __restrict__ W,
              const float* __restrict__ bias, const float* __restrict__ res,
              float* __restrict__ out, int M, int N, int K) {
    extern __shared__ __align__(128) char smem[];
    const uint32_t sbase = smem_u32(smem);
    const int t = threadIdx.x;
    const int warp = t >> 5, lane = t & 31;
    const int wm = warp >> 2;            // 0..1  (64 rows each)
    const int wn = warp & 3;             // 0..3  (32 cols each)
    const int bm = blockIdx.y * 128, bn = blockIdx.x * 128;

    float acc[4][4][4];
    #pragma unroll
    for (int i = 0; i < 4; i++)
        #pragma unroll
        for (int j = 0; j < 4; j++)
            #pragma unroll
            for (int k = 0; k < 4; k++) acc[i][j][k] = 0.f;

    // ---- loader: fp32 global -> bf16 hi/lo smem (padded stride) ----
    auto load_chunk = [&](int ks, int stage) {
        char* st = smem + stage * STAGE_BYTES;
        #pragma unroll
        for (int i = 0; i < 4; i++) {
            int q = t + i * 256;            // 0..1023
            int row = q >> 3, c4 = q & 7;
            size_t gofs = (size_t)row * K + ks * 32 + c4 * 4;
            uint32_t sofs = row * (KPAD * 2) + c4 * 8;

            float4 fa = *(const float4*)(A + (size_t)bm * K + gofs);
            __nv_bfloat162 h0 = __floats2bfloat162_rn(fa.x, fa.y);
            __nv_bfloat162 h1 = __floats2bfloat162_rn(fa.z, fa.w);
            float2 hf0 = __bfloat1622float2(h0);
            float2 hf1 = __bfloat1622float2(h1);
            __nv_bfloat162 l0 = __floats2bfloat162_rn(fa.x - hf0.x, fa.y - hf0.y);
            __nv_bfloat162 l1 = __floats2bfloat162_rn(fa.z - hf1.x, fa.w - hf1.y);
            uint2 hv; hv.x = *(uint32_t*)&h0; hv.y = *(uint32_t*)&h1;
            uint2 lv; lv.x = *(uint32_t*)&l0; lv.y = *(uint32_t*)&l1;
            *(uint2*)(st + sofs) = hv;
            *(uint2*)(st + MAT_BYTES + sofs) = lv;

            float4 fw = *(const float4*)(W + (size_t)bn * K + gofs);
            h0 = __floats2bfloat162_rn(fw.x, fw.y);
            h1 = __floats2bfloat162_rn(fw.z, fw.w);
            hf0 = __bfloat1622float2(h0);
            hf1 = __bfloat1622float2(h1);
            l0 = __floats2bfloat162_rn(fw.x - hf0.x, fw.y - hf0.y);
            l1 = __floats2bfloat162_rn(fw.z - hf1.x, fw.w - hf1.y);
            hv.x = *(uint32_t*)&h0; hv.y = *(uint32_t*)&h1;
            lv.x = *(uint32_t*)&l0; lv.y = *(uint32_t*)&l1;
            *(uint2*)(st + 2 * MAT_BYTES + sofs) = hv;
            *(uint2*)(st + 3 * MAT_BYTES + sofs) = lv;
        }
    };

    const int nk = K >> 5;                 // BK=32
    load_chunk(0, 0);
    __syncthreads();

    // fragment address components (lane-invariant parts)
    const int arow = lane & 15;
    const int aksel = (lane >> 4) << 3;                 // +0 or +8 (k)
    const int brow = (lane & 7) + ((lane >> 4) << 3);   // n within 16
    const int bksel = ((lane >> 3) & 1) << 3;           // +0 or +8 (k)

    for (int ks = 0; ks < nk; ks++) {
        int s = ks & 1;
        uint32_t sA = sbase + s * STAGE_BYTES;
        uint32_t sW = sA + 2 * MAT_BYTES;

        #pragma unroll
        for (int kst = 0; kst < 2; kst++) {
            int ko = kst * 16;
            uint32_t aoff = (uint32_t)(wm * 64 + arow) * (KPAD * 2) + (ko + aksel) * 2;
            uint32_t boff = (uint32_t)(wn * 32 + brow) * (KPAD * 2) + (ko + bksel) * 2;

            uint32_t ah[4][4], bh[2][4];
            #pragma unroll
            for (int mt = 0; mt < 4; mt++)
                ldsm4(ah[mt], sA + aoff + mt * 16 * (KPAD * 2));
            ldsm4(bh[0], sW + boff);
            ldsm4(bh[1], sW + boff + 16 * (KPAD * 2));
            #pragma unroll
            for (int mt = 0; mt < 4; mt++) {
                mma16816(acc[mt][0], ah[mt], bh[0][0], bh[0][1]);
                mma16816(acc[mt][1], ah[mt], bh[0][2], bh[0][3]);
                mma16816(acc[mt][2], ah[mt], bh[1][0], bh[1][1]);
                mma16816(acc[mt][3], ah[mt], bh[1][2], bh[1][3]);
            }

            uint32_t bl[2][4];
            ldsm4(bl[0], sW + MAT_BYTES + boff);
            ldsm4(bl[1], sW + MAT_BYTES + boff + 16 * (KPAD * 2));
            #pragma unroll
            for (int mt = 0; mt < 4; mt++) {
                mma16816(acc[mt][0], ah[mt], bl[0][0], bl[0][1]);
                mma16816(acc[mt][1], ah[mt], bl[0][2], bl[0][3]);
                mma16816(acc[mt][2], ah[mt], bl[1][0], bl[1][1]);
                mma16816(acc[mt][3], ah[mt], bl[1][2], bl[1][3]);
            }

            uint32_t al[4][4];
            #pragma unroll
            for (int mt = 0; mt < 4; mt++)
                ldsm4(al[mt], sA + MAT_BYTES + aoff + mt * 16 * (KPAD * 2));
            #pragma unroll
            for (int mt = 0; mt < 4; mt++) {
                mma16816(acc[mt][0], al[mt], bh[0][0], bh[0][1]);
                mma16816(acc[mt][1], al[mt], bh[0][2], bh[0][3]);
                mma16816(acc[mt][2], al[mt], bh[1][0], bh[1][1]);
                mma16816(acc[mt][3], al[mt], bh[1][2], bh[1][3]);
            }
        }

        if (ks + 1 < nk) load_chunk(ks + 1, s ^ 1);
        __syncthreads();
    }

    // ---- epilogue ----
    const int qrow = lane >> 2, qcol = (lane & 3) * 2;
    #pragma unroll
    for (int mt = 0; mt < 4; mt++) {
        #pragma unroll
        for (int nt = 0; nt < 4; nt++) {
            float* c = acc[mt][nt];
            int col = bn + wn * 32 + nt * 8 + qcol;
            int row0 = bm + wm * 64 + mt * 16 + qrow;
            float2 bv = make_float2(0.f, 0.f);
            if (bias) bv = *(const float2*)(bias + col);
            float v0 = c[0] + bv.x, v1 = c[1] + bv.y;
            float v2 = c[2] + bv.x, v3 = c[3] + bv.y;
            if (ACT == 1) {
                v0 = 0.5f * v0 * (1.0f + erff(v0 * 0.70710678118654752f));
                v1 = 0.5f * v1 * (1.0f + erff(v1 * 0.70710678118654752f));
                v2 = 0.5f * v2 * (1.0f + erff(v2 * 0.70710678118654752f));
                v3 = 0.5f * v3 * (1.0f + erff(v3 * 0.70710678118654752f));
            }
            size_t o0 = (size_t)row0 * N + col;
            size_t o1 = o0 + (size_t)8 * N;
            if (res) {
                float2 r0 = *(const float2*)(res + o0);
                float2 r1 = *(const float2*)(res + o1);
                v0 += r0.x; v1 += r0.y; v2 += r1.x; v3 += r1.y;
            }
            *(float2*)(out + o0) = make_float2(v0, v1);
            *(float2*)(out + o1) = make_float2(v2, v3);
        }
    }
}

// ---------------- Flash attention (fp32) ----------------
#define ATTN_SMEM_FLOATS (64*128 + 64*64 + 64*68 + 128*68)
#define ATTN_SMEM_BYTES  (ATTN_SMEM_FLOATS * 4)

__global__ __launch_bounds__(256)
void attn_kernel(const float* __restrict__ qkv, float* __restrict__ out) {
    extern __shared__ float sm[];
    float* Qt = sm;                       // [64][128] d-major (q pre-scaled)
    float* Kt = Qt + 64*128;              // [64][64]  d-major
    float* Vs = Kt + 64*64;               // [64][68]  n-major (pad 68)
    float* Ps = Vs + 64*68;               // [128][68] r-major (pad 68)

    int tid = threadIdx.x;
    int h = blockIdx.y;
    size_t tb = (size_t)blockIdx.z * NSEQ;
    int q0 = blockIdx.x * 128;

    {
        int r = tid >> 1;
        int c0 = (tid & 1) * 32;
        const float* src = qkv + (tb + q0 + r) * C3 + h * HDIM + c0;
        #pragma unroll
        for (int k = 0; k < 8; k++) {
            float4 v = *(const float4*)(src + k*4);
            int d = c0 + k*4;
            Qt[(d+0)*128 + r] = v.x * 0.125f;
            Qt[(d+1)*128 + r] = v.y * 0.125f;
            Qt[(d+2)*128 + r] = v.z * 0.125f;
            Qt[(d+3)*128 + r] = v.w * 0.125f;
        }
    }

    int ty = tid >> 4, tx = tid & 15;
    float mi[8], li[8], acc[8][4];
    #pragma unroll
    for (int i = 0; i < 8; i++) {
        mi[i] = -1e30f; li[i] = 0.f;
        #pragma unroll
        for (int c = 0; c < 4; c++) acc[i][c] = 0.f;
    }

    for (int n0 = 0; n0 < NSEQ; n0 += 64) {
        {
            int r = tid >> 2;
            int c0 = (tid & 3) * 16;
            const float* ksrc = qkv + (tb + n0 + r) * C3 + CDIM + h * HDIM + c0;
            const float* vsrc = ksrc + CDIM;
            #pragma unroll
            for (int k = 0; k < 4; k++) {
                float4 kv = *(const float4*)(ksrc + k*4);
                int d = c0 + k*4;
                Kt[(d+0)*64 + r] = kv.x;
                Kt[(d+1)*64 + r] = kv.y;
                Kt[(d+2)*64 + r] = kv.z;
                Kt[(d+3)*64 + r] = kv.w;
                float4 vv = *(const float4*)(vsrc + k*4);
                *(float4*)(Vs + r*68 + c0 + k*4) = vv;
            }
        }
        __syncthreads();

        float s[8][4];
        #pragma unroll
        for (int i = 0; i < 8; i++)
            #pragma unroll
            for (int c = 0; c < 4; c++) s[i][c] = 0.f;

        #pragma unroll 8
        for (int d = 0; d < 64; d++) {
            float4 a0 = *(const float4*)(Qt + d*128 + ty*8);
            float4 a1 = *(const float4*)(Qt + d*128 + ty*8 + 4);
            float4 kv = *(const float4*)(Kt + d*64 + tx*4);
            float aa[8] = {a0.x,a0.y,a0.z,a0.w,a1.x,a1.y,a1.z,a1.w};
            float kk[4] = {kv.x,kv.y,kv.z,kv.w};
            #pragma unroll
            for (int i = 0; i < 8; i++)
                #pragma unroll
                for (int c = 0; c < 4; c++)
                    s[i][c] += aa[i] * kk[c];
        }

        #pragma unroll
        for (int i = 0; i < 8; i++) {
            float mx = fmaxf(fmaxf(s[i][0], s[i][1]), fmaxf(s[i][2], s[i][3]));
            #pragma unroll
            for (int mk = 8; mk; mk >>= 1)
                mx = fmaxf(mx, __shfl_xor_sync(0xffffffffu, mx, mk));
            float mnew = fmaxf(mi[i], mx);
            float al = __expf(mi[i] - mnew);
            float p0 = __expf(s[i][0] - mnew);
            float p1 = __expf(s[i][1] - mnew);
            float p2 = __expf(s[i][2] - mnew);
            float p3 = __expf(s[i][3] - mnew);
            float ps = p0 + p1 + p2 + p3;
            #pragma unroll
            for (int mk = 8; mk; mk >>= 1)
                ps += __shfl_xor_sync(0xffffffffu, ps, mk);
            li[i] = li[i] * al + ps;
            mi[i] = mnew;
            acc[i][0] *= al; acc[i][1] *= al; acc[i][2] *= al; acc[i][3] *= al;
            *(float4*)(Ps + (ty*8 + i) * 68 + tx*4) = make_float4(p0, p1, p2, p3);
        }
        __syncthreads();

        #pragma unroll 4
        for (int j4 = 0; j4 < 16; j4++) {
            float4 v0 = *(const float4*)(Vs + (j4*4+0)*68 + tx*4);
            float4 v1 = *(const float4*)(Vs + (j4*4+1)*68 + tx*4);
            float4 v2 = *(const float4*)(Vs + (j4*4+2)*68 + tx*4);
            float4 v3 = *(const float4*)(Vs + (j4*4+3)*68 + tx*4);
            #pragma unroll
            for (int i = 0; i < 8; i++) {
                float4 p = *(const float4*)(Ps + (ty*8 + i) * 68 + j4*4);
                acc[i][0] += p.x*v0.x + p.y*v1.x + p.z*v2.x + p.w*v3.x;
                acc[i][1] += p.x*v0.y + p.y*v1.y + p.z*v2.y + p.w*v3.y;
                acc[i][2] += p.x*v0.z + p.y*v1.z + p.z*v2.z + p.w*v3.z;
                acc[i][3] += p.x*v0.w + p.y*v1.w + p.z*v2.w + p.w*v3.w;
            }
        }
        __syncthreads();
    }

    #pragma unroll
    for (int i = 0; i < 8; i++) {
        float inv = 1.0f / li[i];
        float4 o = make_float4(acc[i][0]*inv, acc[i][1]*inv, acc[i][2]*inv, acc[i][3]*inv);
        *(float4*)(out + (tb + q0 + ty*8 + i) * CDIM + h * HDIM + tx*4) = o;
    }
}

// ---------------- launch ----------------
extern "C" void kernel_launch(void* const* d_in, const int* in_sizes, int n_in,
                              void* d_out, int out_size) {
    const float* x      = (const float*)d_in[0];
    const float* w_qkv  = (const float*)d_in[1];
    const float* w_proj = (const float*)d_in[2];
    const float* b_proj = (const float*)d_in[3];
    const float* ln1_g  = (const float*)d_in[4];
    const float* ln1_b  = (const float*)d_in[5];
    const float* ln2_g  = (const float*)d_in[6];
    const float* ln2_b  = (const float*)d_in[7];
    const float* w_fc1  = (const float*)d_in[8];
    const float* b_fc1  = (const float*)d_in[9];
    const float* w_fc2  = (const float*)d_in[10];
    const float* b_fc2  = (const float*)d_in[11];
    float* out = (float*)d_out;

    float *xn, *qkv, *attn, *x1, *hbuf;
    cudaGetSymbolAddress((void**)&xn,   g_xn);
    cudaGetSymbolAddress((void**)&qkv,  g_qkv);
    cudaGetSymbolAddress((void**)&attn, g_attn);
    cudaGetSymbolAddress((void**)&x1,   g_x1);
    cudaGetSymbolAddress((void**)&hbuf, g_h);

    cudaFuncSetAttribute(attn_kernel, cudaFuncAttributeMaxDynamicSharedMemorySize,
                         ATTN_SMEM_BYTES);
    cudaFuncSetAttribute(gemm_mma<0>, cudaFuncAttributeMaxDynamicSharedMemorySize,
                         GEMM_SMEM);
    cudaFuncSetAttribute(gemm_mma<1>, cudaFuncAttributeMaxDynamicSharedMemorySize,
                         GEMM_SMEM);

    // 1) ln1
    ln_kernel<<<TOK, 256>>>(x, ln1_g, ln1_b, xn);
    // 2) qkv = ln1(x) @ w_qkv^T
    gemm_mma<0><<<dim3(C3/128, TOK/128), 256, GEMM_SMEM>>>(xn, w_qkv, nullptr, nullptr,
                                                           qkv, TOK, C3, CDIM);
    // 3) attention
    attn_kernel<<<dim3(NSEQ/128, NHEAD, BATCH), 256, ATTN_SMEM_BYTES>>>(qkv, attn);
    // 4) x1 = x + attn @ w_proj^T + b_proj
    gemm_mma<0><<<dim3(CDIM/128, TOK/128), 256, GEMM_SMEM>>>(attn, w_proj, b_proj, x,
                                                             x1, TOK, CDIM, CDIM);
    // 5) ln2
    ln_kernel<<<TOK, 256>>>(x1, ln2_g, ln2_b, xn);
    // 6) h = gelu(ln2 @ w_fc1^T + b_fc1)
    gemm_mma<1><<<dim3(HID/128, TOK/128), 256, GEMM_SMEM>>>(xn, w_fc1, b_fc1, nullptr,
                                                            hbuf, TOK, HID, CDIM);
    // 7) out = x1 + h @ w_fc2^T + b_fc2
    gemm_mma<0><<<dim3(CDIM/128, TOK/128), 256, GEMM_SMEM>>>(hbuf, w_fc2, b_fc2, x1,
                                                             out, TOK, CDIM, HID);
}